// round 2
// baseline (speedup 1.0000x reference)
#include <cuda_runtime.h>
#include <math.h>

#define WIDTH 1920
#define BLK 256

// Params: R[9], t[3], fx, fy, cx, cy  -> 16 floats, 4x float4
struct __align__(16) PoseParams {
    float R[9];
    float t[3];
    float fx, fy, cx, cy;
};

__device__ PoseParams g_pp;

__global__ void prep_kernel(const float* __restrict__ x, const float* __restrict__ K) {
    // single thread
    float wx = x[0], wy = x[1], wz = x[2];
    float vx = x[3], vy = x[4], vz = x[5];
    float t2 = wx * wx + wy * wy + wz * wz;
    bool small = t2 < 1e-8f;
    float th = sqrtf(small ? 1.0f : t2);
    float A = small ? (1.0f - t2 / 6.0f) : (sinf(th) / th);
    float B = small ? (0.5f - t2 / 24.0f) : ((1.0f - cosf(th)) / (th * th));
    float C = small ? (1.0f / 6.0f - t2 / 120.0f) : ((th - sinf(th)) / (th * th * th));

    float W[9] = {0.f, -wz, wy,
                  wz, 0.f, -wx,
                  -wy, wx, 0.f};
    float W2[9];
    #pragma unroll
    for (int i = 0; i < 3; i++)
        #pragma unroll
        for (int j = 0; j < 3; j++) {
            float s = 0.f;
            #pragma unroll
            for (int k = 0; k < 3; k++) s += W[i * 3 + k] * W[k * 3 + j];
            W2[i * 3 + j] = s;
        }
    float V[9];
    #pragma unroll
    for (int i = 0; i < 3; i++)
        #pragma unroll
        for (int j = 0; j < 3; j++) {
            float id = (i == j) ? 1.f : 0.f;
            g_pp.R[i * 3 + j] = id + A * W[i * 3 + j] + B * W2[i * 3 + j];
            V[i * 3 + j] = id + B * W[i * 3 + j] + C * W2[i * 3 + j];
        }
    g_pp.t[0] = V[0] * vx + V[1] * vy + V[2] * vz;
    g_pp.t[1] = V[3] * vx + V[4] * vy + V[5] * vz;
    g_pp.t[2] = V[6] * vx + V[7] * vy + V[8] * vz;
    g_pp.fx = K[0];
    g_pp.fy = K[4];
    g_pp.cx = K[2];
    g_pp.cy = K[5];
}

__global__ __launch_bounds__(BLK) void pose_kernel(
    const float* __restrict__ ref_img,
    const float* __restrict__ ref_depth,
    const float* __restrict__ trg_img,
    float* __restrict__ out,
    int H, int N)
{
    __shared__ float s[BLK * 7];
    const int tid = threadIdx.x;
    const int base = blockIdx.x * BLK;
    const int n = base + tid;

    // uniform params (16 floats, 4x LDG.128; L2-resident)
    const float4* pp4 = (const float4*)&g_pp;
    const float4 a0 = pp4[0], a1 = pp4[1], a2 = pp4[2], a3 = pp4[3];
    const float R00 = a0.x, R01 = a0.y, R02 = a0.z, R10 = a0.w;
    const float R11 = a1.x, R12 = a1.y, R20 = a1.z, R21 = a1.w;
    const float R22 = a2.x, t0 = a2.y, t1 = a2.z, t2v = a2.w;
    const float fx = a3.x, fy = a3.y, cx = a3.z, cy = a3.w;

    float o0 = 0.f, o1 = 0.f, o2 = 0.f, o3 = 0.f, o4 = 0.f, o5 = 0.f, o6 = 0.f;

    if (n < N) {
        const int v = n / WIDTH;
        const int u = n - v * WIDTH;
        const float z = __ldg(&ref_depth[n]);

        // pts: exactly ((u - cx) * z) / fx  (mul then true divide, elementwise RN)
        const float px = __fdiv_rn(__fmul_rn((float)u - cx, z), fx);
        const float py = __fdiv_rn(__fmul_rn((float)v - cy, z), fy);
        const float pz = z;

        // p = pts @ R.T + t  (exact for R=I/t=0; chain order matches dot emitter)
        const float q0 = __fadd_rn(__fmaf_rn(pz, R02, __fmaf_rn(py, R01, __fmul_rn(px, R00))), t0);
        const float q1 = __fadd_rn(__fmaf_rn(pz, R12, __fmaf_rn(py, R11, __fmul_rn(px, R10))), t1);
        const float q2 = __fadd_rn(__fmaf_rn(pz, R22, __fmaf_rn(py, R21, __fmul_rn(px, R20))), t2v);

        // proj = p @ K.T  : NON-FUSED mul + add (XLA small-dot emitter, no fp-contract).
        // Middle term * 0 adds +/-0 exactly -> drops out.
        const float pr0 = __fadd_rn(__fmul_rn(q0, fx), __fmul_rn(q2, cx));
        const float pr1 = __fadd_rn(__fmul_rn(q1, fy), __fmul_rn(q2, cy));
        const float pr2 = q2;

        const float uw = __fdiv_rn(pr0, pr2);
        const float vw = __fdiv_rn(pr1, pr2);
        const int ui = __float2int_rz(uw);   // astype(int32): truncate toward zero
        const int vi = __float2int_rz(vw);

        const bool valid = (vi < H) && (ui < WIDTH) && (vi > 0) && (ui > 0);

        if (valid) {
            // when valid, clip is a no-op (indices already in-range)
            const float warped = __ldg(&ref_img[vi * WIDTH + ui]);
            const float tc = __ldg(&trg_img[n]);
            o0 = __fsub_rn(warped, tc);

            // Sobel grads are zero on a 2px border (crop+pad in reference) -> J = 0 there
            if (u >= 2 && u < WIDTH - 2 && v >= 2 && v < H - 2) {
                const float* rm = trg_img + (v - 1) * WIDTH + u;
                const float* rc = trg_img + v * WIDTH + u;
                const float* rp = trg_img + (v + 1) * WIDTH + u;
                const float tA = __ldg(rm - 1), tB = __ldg(rm), tC = __ldg(rm + 1);
                const float tD = __ldg(rc - 1),                 tE = __ldg(rc + 1);
                const float tF = __ldg(rp - 1), tG = __ldg(rp), tH = __ldg(rp + 1);

                const float gx = 0.125f * (tC - tA) + 0.25f * (tE - tD) + 0.125f * (tH - tF);
                const float gy = 0.125f * (tF - tA) + 0.25f * (tG - tB) + 0.125f * (tH - tC);

                const float zi  = __fdiv_rn(1.0f, pz);
                const float xzi = px * zi;                 // xp * zi
                const float yzi = py * zi;                 // yp * zi
                const float fgx = fx * gx;                 // NOTE: reference uses fx for BOTH rows
                const float fgy = fx * gy;

                // J = gx * Jw_row0 + gy * Jw_row1
                o1 = -(fgx * (xzi * yzi) + fgy * (1.0f + yzi * yzi));
                o2 =   fgx * (1.0f + xzi * xzi) + fgy * (xzi * yzi);
                o3 =   fgy * xzi - fgx * yzi;
                o4 =   fgx * zi;
                o5 =   fgy * zi;
                o6 = -(fgx * xzi + fgy * yzi) * zi;
            }
        }
    }

    // stage (stride-7 smem: conflict-free), then coalesced float4 stores
    const int si = tid * 7;
    s[si + 0] = o0; s[si + 1] = o1; s[si + 2] = o2; s[si + 3] = o3;
    s[si + 4] = o4; s[si + 5] = o5; s[si + 6] = o6;
    __syncthreads();

    const int fbase = base * 7;                 // divisible by 4 (7*256 = 1792)
    const int cnt = min(BLK * 7, (N - base) * 7);
    if (cnt == BLK * 7) {
        float4* o4p = (float4*)(out + fbase);
        const float4* s4 = (const float4*)s;
        o4p[tid] = s4[tid];
        const int i2 = tid + BLK;
        if (i2 < (BLK * 7) / 4) o4p[i2] = s4[i2];
    } else {
        for (int i = tid; i < cnt; i += BLK) out[fbase + i] = s[i];
    }
}

extern "C" void kernel_launch(void* const* d_in, const int* in_sizes, int n_in,
                              void* d_out, int out_size) {
    const float* x         = (const float*)d_in[0];
    const float* ref_img   = (const float*)d_in[1];
    const float* ref_depth = (const float*)d_in[2];
    const float* trg_img   = (const float*)d_in[3];
    const float* K         = (const float*)d_in[4];

    const int N = in_sizes[1];          // H*W
    const int H = N / WIDTH;            // W fixed at 1920 for this problem

    prep_kernel<<<1, 1>>>(x, K);
    const int blocks = (N + BLK - 1) / BLK;
    pose_kernel<<<blocks, BLK>>>(ref_img, ref_depth, trg_img, (float*)d_out, H, N);
}

// round 3
// speedup vs baseline: 1.2484x; 1.2484x over previous
#include <cuda_runtime.h>
#include <math.h>

#define IMG_W   1920
#define BX      128
#define TILE_F4 34            // float4 per smem row: covers cols [u0-4, u0+131]
#define TILE_W  (TILE_F4 * 4)

// Params: R[9], t[3], fx, fy, cx, cy  -> 16 floats, 4x float4
struct __align__(16) PoseParams {
    float R[9];
    float t[3];
    float fx, fy, cx, cy;
};

__device__ PoseParams g_pp;

__global__ void prep_kernel(const float* __restrict__ x, const float* __restrict__ K) {
    float wx = x[0], wy = x[1], wz = x[2];
    float vx = x[3], vy = x[4], vz = x[5];
    float t2 = wx * wx + wy * wy + wz * wz;
    bool small = t2 < 1e-8f;
    float th = sqrtf(small ? 1.0f : t2);
    float A = small ? (1.0f - t2 / 6.0f) : (sinf(th) / th);
    float B = small ? (0.5f - t2 / 24.0f) : ((1.0f - cosf(th)) / (th * th));
    float C = small ? (1.0f / 6.0f - t2 / 120.0f) : ((th - sinf(th)) / (th * th * th));

    float W[9] = {0.f, -wz, wy,
                  wz, 0.f, -wx,
                  -wy, wx, 0.f};
    float W2[9];
    #pragma unroll
    for (int i = 0; i < 3; i++)
        #pragma unroll
        for (int j = 0; j < 3; j++) {
            float s = 0.f;
            #pragma unroll
            for (int k = 0; k < 3; k++) s += W[i * 3 + k] * W[k * 3 + j];
            W2[i * 3 + j] = s;
        }
    float V[9];
    #pragma unroll
    for (int i = 0; i < 3; i++)
        #pragma unroll
        for (int j = 0; j < 3; j++) {
            float id = (i == j) ? 1.f : 0.f;
            g_pp.R[i * 3 + j] = id + A * W[i * 3 + j] + B * W2[i * 3 + j];
            V[i * 3 + j] = id + B * W[i * 3 + j] + C * W2[i * 3 + j];
        }
    g_pp.t[0] = V[0] * vx + V[1] * vy + V[2] * vz;
    g_pp.t[1] = V[3] * vx + V[4] * vy + V[5] * vz;
    g_pp.t[2] = V[6] * vx + V[7] * vy + V[8] * vz;
    g_pp.fx = K[0];
    g_pp.fy = K[4];
    g_pp.cx = K[2];
    g_pp.cy = K[5];
}

__global__ __launch_bounds__(BX, 12) void pose_kernel(
    const float* __restrict__ ref_img,
    const float* __restrict__ ref_depth,
    const float* __restrict__ trg_img,
    float* __restrict__ out,
    int H)
{
    __shared__ float st[3][TILE_W];   // trg rows v-1, v, v+1 over [u0-4, u0+131]
    __shared__ float so[BX * 7];      // output staging

    const int tid = threadIdx.x;
    const int u0  = blockIdx.x * BX;
    const int v   = blockIdx.y;
    const int u   = u0 + tid;
    const int n   = v * IMG_W + u;

    // ---- cooperative trg tile load: 3 rows x 34 float4 ----
    for (int idx = tid; idx < 3 * TILE_F4; idx += BX) {
        const int r  = idx / TILE_F4;
        const int c  = idx - r * TILE_F4;
        int gr = v + r - 1;
        gr = min(max(gr, 0), H - 1);           // clamped rows only feed unused border lanes
        const int gc = u0 - 4 + c * 4;
        float4 val = make_float4(0.f, 0.f, 0.f, 0.f);
        if (gc >= 0 && gc + 3 < IMG_W)
            val = *reinterpret_cast<const float4*>(trg_img + gr * IMG_W + gc);
        *reinterpret_cast<float4*>(&st[r][c * 4]) = val;
    }
    __syncthreads();

    // ---- uniforms ----
    const float4* pp4 = (const float4*)&g_pp;
    const float4 a0 = pp4[0], a1 = pp4[1], a2 = pp4[2], a3 = pp4[3];
    const float R00 = a0.x, R01 = a0.y, R02 = a0.z, R10 = a0.w;
    const float R11 = a1.x, R12 = a1.y, R20 = a1.z, R21 = a1.w;
    const float R22 = a2.x, t0 = a2.y, t1 = a2.z, t2v = a2.w;
    const float fx = a3.x, fy = a3.y, cx = a3.z, cy = a3.w;

    float o0 = 0.f, o1 = 0.f, o2 = 0.f, o3 = 0.f, o4 = 0.f, o5 = 0.f, o6 = 0.f;

    {
        const float z = __ldg(&ref_depth[n]);

        // ---- FROZEN index path: bit-exact vs reference ----
        const float px = __fdiv_rn(__fmul_rn((float)u - cx, z), fx);
        const float py = __fdiv_rn(__fmul_rn((float)v - cy, z), fy);
        const float pz = z;

        const float q0 = __fadd_rn(__fmaf_rn(pz, R02, __fmaf_rn(py, R01, __fmul_rn(px, R00))), t0);
        const float q1 = __fadd_rn(__fmaf_rn(pz, R12, __fmaf_rn(py, R11, __fmul_rn(px, R10))), t1);
        const float q2 = __fadd_rn(__fmaf_rn(pz, R22, __fmaf_rn(py, R21, __fmul_rn(px, R20))), t2v);

        // proj = p @ K.T : NON-FUSED mul + add (matches reference rounding)
        const float pr0 = __fadd_rn(__fmul_rn(q0, fx), __fmul_rn(q2, cx));
        const float pr1 = __fadd_rn(__fmul_rn(q1, fy), __fmul_rn(q2, cy));
        const float pr2 = q2;

        const float uw = __fdiv_rn(pr0, pr2);
        const float vw = __fdiv_rn(pr1, pr2);
        const int ui = __float2int_rz(uw);
        const int vi = __float2int_rz(vw);
        // ---- end frozen path ----

        const bool valid = (vi < H) && (ui < IMG_W) && (vi > 0) && (ui > 0);

        if (valid) {
            const float warped = __ldg(&ref_img[vi * IMG_W + ui]);
            const float tc = st[1][tid + 4];           // == trg_img[n]
            o0 = __fsub_rn(warped, tc);

            if (u >= 2 && u < IMG_W - 2 && v >= 2 && v < H - 2) {
                const int cm = tid + 3;                 // col u-1 in smem
                const float tA = st[0][cm], tB = st[0][cm + 1], tC = st[0][cm + 2];
                const float tD = st[1][cm],                     tE = st[1][cm + 2];
                const float tF = st[2][cm], tG = st[2][cm + 1], tH = st[2][cm + 2];

                const float gx = 0.125f * (tC - tA) + 0.25f * (tE - tD) + 0.125f * (tH - tF);
                const float gy = 0.125f * (tF - tA) + 0.25f * (tG - tB) + 0.125f * (tH - tC);

                const float zi  = __fdividef(1.0f, pz);     // J path: approx ok (~2^-22)
                const float xzi = px * zi;
                const float yzi = py * zi;
                const float fgx = fx * gx;                  // reference uses fx for BOTH rows
                const float fgy = fx * gy;

                o1 = -(fgx * (xzi * yzi) + fgy * (1.0f + yzi * yzi));
                o2 =   fgx * (1.0f + xzi * xzi) + fgy * (xzi * yzi);
                o3 =   fgy * xzi - fgx * yzi;
                o4 =   fgx * zi;
                o5 =   fgy * zi;
                o6 = -(fgx * xzi + fgy * yzi) * zi;
            }
        }
    }

    // ---- stage (stride-7: conflict-free) then coalesced streaming float4 stores ----
    const int si = tid * 7;
    so[si + 0] = o0; so[si + 1] = o1; so[si + 2] = o2; so[si + 3] = o3;
    so[si + 4] = o4; so[si + 5] = o5; so[si + 6] = o6;
    __syncthreads();

    float* obase = out + (size_t)n * 0 + ((size_t)v * IMG_W + u0) * 7;  // (v*W + u0)*7, mult of 4
    const float4* s4 = (const float4*)so;
    float4* o4p = (float4*)obase;
    __stcs(&o4p[tid], s4[tid]);
    const int i2 = tid + BX;
    if (i2 < (BX * 7) / 4) __stcs(&o4p[i2], s4[i2]);
}

extern "C" void kernel_launch(void* const* d_in, const int* in_sizes, int n_in,
                              void* d_out, int out_size) {
    const float* x         = (const float*)d_in[0];
    const float* ref_img   = (const float*)d_in[1];
    const float* ref_depth = (const float*)d_in[2];
    const float* trg_img   = (const float*)d_in[3];
    const float* K         = (const float*)d_in[4];

    const int N = in_sizes[1];          // H*W
    const int H = N / IMG_W;            // W fixed at 1920

    prep_kernel<<<1, 1>>>(x, K);
    dim3 grid(IMG_W / BX, H);
    pose_kernel<<<grid, BX>>>(ref_img, ref_depth, trg_img, (float*)d_out, H);
}